// round 12
// baseline (speedup 1.0000x reference)
#include <cuda_runtime.h>
#include <cstdint>

// ---------------------------------------------------------------------------
// AnisotropicDistance: out[b,i,j] = alpha_i * max(||d||^2 + a^2*(|t_i|^2-2), 0)
//                                 + beta_i * a^2,  d = p_i - p_j, a = d . t_i
// B=2, N=8192 -> 537MB fp32 output: DRAM-write + issue bound.
// R11: alpha pre-scaled into row constants (alpha*max(x,0)=max(alpha*x,0),
//      alpha>0) -> 11 ops/element; pointer-increment addressing to cut ALU.
//      Memory shape unchanged from R7 (SoA j loads, STG.128 streaming stores).
// ---------------------------------------------------------------------------

#define MAX_BN 32768

// SoA j-side data (component arrays -> coalesced float4 loads of 4 cols)
__device__ float g_px[MAX_BN];
__device__ float g_py[MAX_BN];
__device__ float g_pz[MAX_BN];
__device__ float g_pw[MAX_BN];   // |p|^2

// Per-row constants (uniform broadcast loads), alpha pre-scaled
__device__ float4 g_q0[MAX_BN];  // (-tx, -ty, -tz, p.t)
__device__ float4 g_q1[MAX_BN];  // (-2a*px, -2a*py, -2a*pz, a*|p|^2)   a=alpha
__device__ float4 g_q2[MAX_BN];  // (D = a*(|t|^2-2), alpha, beta, 0)

__global__ void pack_kernel(const float* __restrict__ pts,
                            const float* __restrict__ pd,
                            const float* __restrict__ lin, int BN) {
    int n = blockIdx.x * blockDim.x + threadIdx.x;
    if (n >= BN) return;
    float px = pts[3 * n + 0], py = pts[3 * n + 1], pz = pts[3 * n + 2];
    float tx = pd[3 * n + 0],  ty = pd[3 * n + 1],  tz = pd[3 * n + 2];
    float l  = lin[n];
    float sq     = fmaf(px, px, fmaf(py, py, pz * pz));
    float tn2    = fmaf(tx, tx, fmaf(ty, ty, tz * tz));
    float pdself = fmaf(px, tx, fmaf(py, ty, pz * tz));
    float alpha  = 2.0f * (1.0f + l);
    float beta   = 0.5f * (1.0f - l);
    g_px[n] = px; g_py[n] = py; g_pz[n] = pz; g_pw[n] = sq;
    g_q0[n] = make_float4(-tx, -ty, -tz, pdself);
    g_q1[n] = make_float4(-2.0f * alpha * px, -2.0f * alpha * py,
                          -2.0f * alpha * pz, alpha * sq);
    g_q2[n] = make_float4(alpha * (tn2 - 2.0f), alpha, beta, 0.0f);
}

constexpr int TI      = 32;            // i-rows per block
constexpr int THREADS = 256;
constexpr int TJ      = 4;             // consecutive j-cols per thread
constexpr int JSPAN   = THREADS * TJ;  // 1024 cols per block

__global__ __launch_bounds__(THREADS, 6)
void dist_kernel(float* __restrict__ out, int N) {
    const int b    = blockIdx.z;
    const int i0   = blockIdx.y * TI;
    const int j0   = blockIdx.x * JSPAN + threadIdx.x * TJ;  // 4 consecutive
    const int base = b * N;

    // j-tile: 4 coalesced LDG.128 (16B inter-thread stride) from SoA arrays.
    const float4 X = *reinterpret_cast<const float4*>(&g_px[base + j0]);
    const float4 Y = *reinterpret_cast<const float4*>(&g_py[base + j0]);
    const float4 Z = *reinterpret_cast<const float4*>(&g_pz[base + j0]);
    const float4 W = *reinterpret_cast<const float4*>(&g_pw[base + j0]);

    // Pointer-increment addressing: one 64-bit add per row.
    float* orow = out + (((size_t)b * N + (size_t)i0) * (size_t)N + (size_t)j0);

#pragma unroll 4
    for (int ii = 0; ii < TI; ii++) {
        // Uniform-address loads -> L1 broadcast, L2 resident.
        const int    r  = base + i0 + ii;
        const float4 A  = g_q0[r];
        const float4 Bv = g_q1[r];   // alpha-scaled
        const float4 C  = g_q2[r];   // (D, alpha, beta, 0)

        float o[TJ];
#define COL(k, cx, cy, cz, cw)                                               \
        {                                                                     \
            float along = fmaf(cx, A.x, fmaf(cy, A.y, fmaf(cz, A.z, A.w)));  \
            float a2    = along * along;                                      \
            float u     = fmaf(C.y, cw, Bv.w);          /* a*|pj|^2+a*|pi|^2 */\
            float s     = fmaf(cx, Bv.x, fmaf(cy, Bv.y, fmaf(cz, Bv.z, u))); \
            float s2    = fmaf(a2, C.x, s);             /* a*(sqd+a2*(t2-2)) */\
            o[k] = fmaf(C.z, a2, fmaxf(s2, 0.0f));                            \
        }
        COL(0, X.x, Y.x, Z.x, W.x)
        COL(1, X.y, Y.y, Z.y, W.y)
        COL(2, X.z, Y.z, Z.z, W.z)
        COL(3, X.w, Y.w, Z.w, W.w)
#undef COL
        // One coalesced streaming STG.128 per row (write-once output).
        __stcs(reinterpret_cast<float4*>(orow),
               make_float4(o[0], o[1], o[2], o[3]));
        orow += N;
    }
}

// Fallback for shapes not divisible by the tile (not expected for N=8192).
__global__ void dist_kernel_generic(float* __restrict__ out, int N, int Btot) {
    int64_t idx = (int64_t)blockIdx.x * blockDim.x + threadIdx.x;
    int64_t total = (int64_t)Btot * N * N;
    if (idx >= total) return;
    int j = (int)(idx % N);
    int64_t t = idx / N;
    int i = (int)(t % N);
    int b = (int)(t / N);
    int r = b * N + i;
    float4 A  = g_q0[r];
    float4 Bv = g_q1[r];
    float4 C  = g_q2[r];
    int jj = b * N + j;
    float px = g_px[jj], py = g_py[jj], pz = g_pz[jj], pw = g_pw[jj];
    float along = fmaf(px, A.x, fmaf(py, A.y, fmaf(pz, A.z, A.w)));
    float a2    = along * along;
    float u     = fmaf(C.y, pw, Bv.w);
    float s     = fmaf(px, Bv.x, fmaf(py, Bv.y, fmaf(pz, Bv.z, u)));
    float s2    = fmaf(a2, C.x, s);
    out[idx]    = fmaf(C.z, a2, fmaxf(s2, 0.0f));
}

extern "C" void kernel_launch(void* const* d_in, const int* in_sizes, int n_in,
                              void* d_out, int out_size) {
    const float* points = (const float*)d_in[0];
    const float* pdir   = (const float*)d_in[1];
    const float* lin    = (const float*)d_in[2];
    float* out = (float*)d_out;

    const int BN = in_sizes[2];              // B*N (linearity has 1 elem/point)
    const int N  = (int)((long long)out_size / BN);
    const int B  = BN / N;

    pack_kernel<<<(BN + 255) / 256, 256>>>(points, pdir, lin, BN);

    if ((N % JSPAN) == 0 && (N % TI) == 0) {
        dim3 grid(N / JSPAN, N / TI, B);
        dist_kernel<<<grid, THREADS>>>(out, N);
    } else {
        int64_t total = (int64_t)B * N * N;
        int64_t blocks = (total + 255) / 256;
        dist_kernel_generic<<<(unsigned)blocks, 256>>>(out, N, B);
    }
}